// round 1
// baseline (speedup 1.0000x reference)
#include <cuda_runtime.h>

#define B 32
#define N 2048
#define C 64
#define R 32
#define K 64

// Scratch (allocation-free rule: __device__ globals)
__device__ float g_pv[B * N];     // dense top-k vector per batch
__device__ float g_vals[B * K];
__device__ int   g_idx[B * K];

// ---------------------------------------------------------------------------
// Kernel 1: per-row bitonic sort (descending, ties -> lower index first),
// emit topk_vals, topk_idx, and the dense pv vector.
// One block per batch row, 1024 threads, 2048-element sort in shared.
// ---------------------------------------------------------------------------
__global__ __launch_bounds__(1024)
void topk_kernel(const float* __restrict__ acc, float* __restrict__ out) {
    __shared__ float sv[N];
    __shared__ int   si[N];
    const int b = blockIdx.x;
    const int tid = threadIdx.x;

    const float* row = acc + b * N;
    for (int p = tid; p < N; p += 1024) { sv[p] = row[p]; si[p] = p; }
    __syncthreads();

    // Bitonic sort, full network. Final order: descending by value,
    // ascending by index on ties (matches jax.lax.top_k).
    for (int k = 2; k <= N; k <<= 1) {
        for (int j = k >> 1; j > 0; j >>= 1) {
            for (int p = tid; p < N; p += 1024) {
                int q = p ^ j;
                if (q > p) {
                    float va = sv[p], vb = sv[q];
                    int   ia = si[p], ib = si[q];
                    bool a_first = (va > vb) || (va == vb && ia < ib);
                    bool desc = ((p & k) == 0);
                    if (desc ? !a_first : a_first) {
                        sv[p] = vb; sv[q] = va;
                        si[p] = ib; si[q] = ia;
                    }
                }
            }
            __syncthreads();
        }
    }

    // zero pv row, then scatter top-K
    for (int p = tid; p < N; p += 1024) g_pv[b * N + p] = 0.0f;
    __syncthreads();

    if (tid < K) {
        float v  = sv[tid];
        int   id = si[tid];
        out[b * K + tid]          = v;           // topk_vals
        out[B * K + b * K + tid]  = (float)id;   // topk_idx (cast to out dtype)
        g_vals[b * K + tid] = v;
        g_idx [b * K + tid] = id;
        g_pv  [b * N + id]  = v;
    }
}

// ---------------------------------------------------------------------------
// Kernel 2: frob[b,c] = sum_r ( sum_k vals[k] * U[c, idx[k], r] )^2 / (K*R)
// One block per batch. Warp w handles channels {w, w+32}; lane = r.
// Loads of U[c*N*R + idx*R + r] are fully coalesced across the warp (r fastest).
// ---------------------------------------------------------------------------
__global__ __launch_bounds__(1024)
void frob_kernel(const float* __restrict__ U, float* __restrict__ out) {
    __shared__ float s_vals[K];
    __shared__ int   s_idx[K];
    const int b = blockIdx.x;
    const int tid = threadIdx.x;

    if (tid < K) { s_vals[tid] = g_vals[b * K + tid]; s_idx[tid] = g_idx[b * K + tid]; }
    __syncthreads();

    const int r = tid & 31;
    const int w = tid >> 5;   // 0..31

    #pragma unroll
    for (int cc = 0; cc < 2; cc++) {
        const int c = w + cc * 32;
        const float* Uc = U + (size_t)c * N * R;
        float au = 0.0f;
        #pragma unroll 8
        for (int k = 0; k < K; k++)
            au = fmaf(s_vals[k], Uc[(size_t)s_idx[k] * R + r], au);
        float sq = au * au;
        #pragma unroll
        for (int o = 16; o > 0; o >>= 1)
            sq += __shfl_xor_sync(0xffffffffu, sq, o);
        if (r == 0) out[2 * B * K + b * C + c] = sq / (float)(K * R);
    }
}

// ---------------------------------------------------------------------------
// Kernel 3: M[b,i,j] = pv[b][i] * pv[b][j]  — pure streaming 512 MiB store.
// Each block: 16 rows of one batch. pv row cached once in shared (8 KB),
// float4 stores, 2 per thread per row.
// Grid: (N/16, B) = (128, 32) blocks x 256 threads.
// ---------------------------------------------------------------------------
__global__ __launch_bounds__(256)
void M_kernel(float* __restrict__ outM) {
    __shared__ float s_pv[N];
    const int b    = blockIdx.y;
    const int tile = blockIdx.x;    // 16 rows per tile
    const int tid  = threadIdx.x;

    const float4* pv4 = reinterpret_cast<const float4*>(g_pv + b * N);
    float4* s4 = reinterpret_cast<float4*>(s_pv);
    for (int q = tid; q < N / 4; q += 256) s4[q] = pv4[q];
    __syncthreads();

    float4* out4 = reinterpret_cast<float4*>(outM);
    #pragma unroll
    for (int ir = 0; ir < 16; ir++) {
        const int i = tile * 16 + ir;
        const float pvi = s_pv[i];
        const size_t base = ((size_t)b * N + i) * (N / 4);
        #pragma unroll
        for (int jj = 0; jj < 2; jj++) {
            const int j4 = tid + jj * 256;
            float4 v = s4[j4];
            out4[base + j4] = make_float4(pvi * v.x, pvi * v.y, pvi * v.z, pvi * v.w);
        }
    }
}

extern "C" void kernel_launch(void* const* d_in, const int* in_sizes, int n_in,
                              void* d_out, int out_size) {
    const float* acc = (const float*)d_in[0];   // [B, N] float32
    const float* U   = (const float*)d_in[1];   // [C, N, R] float32
    float* out = (float*)d_out;

    topk_kernel<<<B, 1024>>>(acc, out);
    frob_kernel<<<B, 1024>>>(U, out);
    M_kernel<<<dim3(N / 16, B), 256>>>(out + 3 * B * K);  // offset 6144 floats
}

// round 2
// speedup vs baseline: 1.2628x; 1.2628x over previous
#include <cuda_runtime.h>

#define B 32
#define N 2048
#define C 64
#define R 32
#define K 64

__device__ float g_pv[B * N];     // dense top-k vector per batch

// total-order "a before b" in descending-value, ascending-index order
__device__ __forceinline__ bool tfirst(float va, int ia, float vb, int ib) {
    return (va > vb) || (va == vb && ia < ib);
}

// shuffle compare-exchange on element e = lane (+32r); partner differs in lane bit j
__device__ __forceinline__ void cmpx(float& v, int& i, int j, bool desc) {
    float ov = __shfl_xor_sync(0xffffffffu, v, j);
    int   oi = __shfl_xor_sync(0xffffffffu, i, j);
    bool lower = ((threadIdx.x & 31 & j) == 0);
    bool mine_first = tfirst(v, i, ov, oi);
    if (mine_first != (lower == desc)) { v = ov; i = oi; }
}

// ---------------------------------------------------------------------------
// Fused kernel: warp-register bitonic top-K + frob. One block per batch row.
// ---------------------------------------------------------------------------
__global__ __launch_bounds__(1024)
void topk_frob_kernel(const float* __restrict__ acc,
                      const float* __restrict__ U,
                      float* __restrict__ out) {
    __shared__ float sv[N];
    __shared__ int   si[N];
    const int b    = blockIdx.x;
    const int tid  = threadIdx.x;
    const int lane = tid & 31;
    const int w    = tid >> 5;           // warp 0..31

    // zero pv row early (independent of the sort)
    g_pv[b * N + tid] = 0.0f;
    g_pv[b * N + tid + 1024] = 0.0f;

    // ---- load chunk w: elements e0=lane, e1=lane+32 of a 64-elem list ----
    const float* row = acc + b * N;
    float v0 = row[w * 64 + lane];        int i0 = w * 64 + lane;
    float v1 = row[w * 64 + 32 + lane];   int i1 = w * 64 + 32 + lane;

    // ---- bitonic sort 64 elements in-warp (descending, tie: idx asc) ----
    #pragma unroll
    for (int k = 2; k <= 32; k <<= 1) {
        #pragma unroll
        for (int j = k >> 1; j >= 1; j >>= 1) {
            cmpx(v0, i0, j, ((lane)      & k) == 0);
            cmpx(v1, i1, j, ((lane + 32) & k) == 0);
        }
    }
    // k = 64 level: j=32 is a register swap (e0<e1, desc)
    if (!tfirst(v0, i0, v1, i1)) {
        float tv = v0; v0 = v1; v1 = tv;
        int   ti = i0; i0 = i1; i1 = ti;
    }
    #pragma unroll
    for (int j = 16; j >= 1; j >>= 1) { cmpx(v0, i0, j, true); cmpx(v1, i1, j, true); }

    // stash sorted chunk
    sv[w * 64 + lane] = v0;  si[w * 64 + lane] = i0;
    sv[w * 64 + 32 + lane] = v1;  si[w * 64 + 32 + lane] = i1;
    __syncthreads();

    // ---- 5 merge rounds: keep top-64 of pairs of sorted-desc 64-lists ----
    #pragma unroll
    for (int t = 0; t < 5; t++) {
        const int nw = 16 >> t;
        if (w < nw) {
            const int la = 2 * w, lb = 2 * w + 1;
            float a0 = sv[la * 64 + lane];       int a0i = si[la * 64 + lane];
            float a1 = sv[la * 64 + 32 + lane];  int a1i = si[la * 64 + 32 + lane];
            float b0 = sv[lb * 64 + lane];       int b0i = si[lb * 64 + lane];
            float b1 = sv[lb * 64 + 32 + lane];  int b1i = si[lb * 64 + 32 + lane];
            // C[e] = totalmax(A[e], B[63-e]);  B[63-lane] -> b1 @ lane^31, B[31-lane] -> b0 @ lane^31
            float m0 = __shfl_xor_sync(0xffffffffu, b1, 31);
            int  m0i = __shfl_xor_sync(0xffffffffu, b1i, 31);
            float m1 = __shfl_xor_sync(0xffffffffu, b0, 31);
            int  m1i = __shfl_xor_sync(0xffffffffu, b0i, 31);
            if (!tfirst(a0, a0i, m0, m0i)) { a0 = m0; a0i = m0i; }
            if (!tfirst(a1, a1i, m1, m1i)) { a1 = m1; a1i = m1i; }
            // bitonic merge, descending
            if (!tfirst(a0, a0i, a1, a1i)) {
                float tv = a0; a0 = a1; a1 = tv;
                int   ti = a0i; a0i = a1i; a1i = ti;
            }
            #pragma unroll
            for (int j = 16; j >= 1; j >>= 1) { cmpx(a0, a0i, j, true); cmpx(a1, a1i, j, true); }
            sv[w * 64 + lane] = a0;       si[w * 64 + lane] = a0i;
            sv[w * 64 + 32 + lane] = a1;  si[w * 64 + 32 + lane] = a1i;
        }
        __syncthreads();
    }

    // ---- emit topk outputs + pv scatter (warp 0 holds final list in sv[0..63]) ----
    if (tid < K) {
        float v  = sv[tid];
        int   id = si[tid];
        out[b * K + tid]         = v;
        out[B * K + b * K + tid] = (float)id;
        g_pv[b * N + id]         = v;
    }
    __syncthreads();

    // ---- frob: warp w -> channels {w, w+32}, lane = r ----
    const int r = lane;
    #pragma unroll
    for (int cc = 0; cc < 2; cc++) {
        const int c = w + cc * 32;
        const float* Uc = U + (size_t)c * N * R;
        float au = 0.0f;
        #pragma unroll 8
        for (int k = 0; k < K; k++)
            au = fmaf(sv[k], Uc[(size_t)si[k] * R + r], au);
        float sq = au * au;
        #pragma unroll
        for (int o = 16; o > 0; o >>= 1)
            sq += __shfl_xor_sync(0xffffffffu, sq, o);
        if (r == 0) out[2 * B * K + b * C + c] = sq / (float)(K * R);
    }
}

// ---------------------------------------------------------------------------
// M[b,i,j] = pv[b][i] * pv[b][j] — streaming 512 MiB store at the HBM roofline.
// ---------------------------------------------------------------------------
__global__ __launch_bounds__(256)
void M_kernel(float* __restrict__ outM) {
    __shared__ float s_pv[N];
    const int b    = blockIdx.y;
    const int tile = blockIdx.x;    // 16 rows per tile
    const int tid  = threadIdx.x;

    const float4* pv4 = reinterpret_cast<const float4*>(g_pv + b * N);
    float4* s4 = reinterpret_cast<float4*>(s_pv);
    for (int q = tid; q < N / 4; q += 256) s4[q] = pv4[q];
    __syncthreads();

    float4* out4 = reinterpret_cast<float4*>(outM);
    #pragma unroll
    for (int ir = 0; ir < 16; ir++) {
        const int i = tile * 16 + ir;
        const float pvi = s_pv[i];
        const size_t base = ((size_t)b * N + i) * (N / 4);
        #pragma unroll
        for (int jj = 0; jj < 2; jj++) {
            const int j4 = tid + jj * 256;
            float4 v = s4[j4];
            float4 o = make_float4(pvi * v.x, pvi * v.y, pvi * v.z, pvi * v.w);
            __stcs(&out4[base + j4], o);
        }
    }
}

extern "C" void kernel_launch(void* const* d_in, const int* in_sizes, int n_in,
                              void* d_out, int out_size) {
    const float* acc = (const float*)d_in[0];   // [B, N] float32
    const float* U   = (const float*)d_in[1];   // [C, N, R] float32
    float* out = (float*)d_out;

    topk_frob_kernel<<<B, 1024>>>(acc, U, out);
    M_kernel<<<dim3(N / 16, B), 256>>>(out + 3 * B * K);
}